// round 12
// baseline (speedup 1.0000x reference)
#include <cuda_runtime.h>
#include <stdint.h>

#define B_      8
#define IN_CH   64
#define OUT_CH  64
#define GROUPS  8
#define FPG     8
#define OPG     8
#define H_      256
#define W_      256

#define TY      8            // output rows per block
#define HYR     (TY + 2)     // halo rows = 10
#define SW      264          // smem row: 4 pad | 256 | 4 pad (16B-aligned)
#define NT      128          // threads per block

// Block = (b, g, 8-row full-width stripe), 128 threads (4 warps).
//  - threads 0..71 compute the (b,g) dynamic weights (issued first, overlaps loads)
//  - interior halo: 10 rows x 64 aligned float4 quads = 640 = 128 x 5 -> exactly
//    5 unpredicated iterations, 8 LDG.128 each (high MLP)
//  - compute: thread owns 4 cols x 4 rows x 8 oc, float4 stores
__global__ __launch_bounds__(NT, 16)
void dynconv_kernel(const float* __restrict__ x,
                    const float* __restrict__ rep,
                    const float* __restrict__ Wm,
                    float* __restrict__ out) {
    __shared__ float S[HYR][SW];       // 10 x 264 x 4B = 10560 B
    __shared__ float kw[OPG][9];

    const int bg  = blockIdx.y;        // 0..63
    const int b   = bg >> 3;
    const int g   = bg & 7;
    const int ty0 = blockIdx.x * TY;
    const int tid = threadIdx.x;       // 0..127

    // ---- dynamic weights for this (b,g): threads 0..71 ----
    if (tid < OPG * 9) {
        const int ocl = tid / 9;
        const int tap = tid - ocl * 9;
        const float4* r  = (const float4*)(rep + b * 32);
        const float4* wv = (const float4*)(Wm + ((size_t)((g * OPG + ocl) * 9 + tap)) * 32);
        float s = 0.f;
#pragma unroll
        for (int i = 0; i < 8; i++) {
            float4 rv = r[i], ww = wv[i];
            s = fmaf(rv.x, ww.x, s);
            s = fmaf(rv.y, ww.y, s);
            s = fmaf(rv.z, ww.z, s);
            s = fmaf(rv.w, ww.w, s);
        }
        kw[ocl][tap] = (s > 0.f) ? s : 0.1f * s;
    }

    const size_t plane  = (size_t)H_ * W_;
    const size_t plane4 = plane / 4;
    const float* xg = x + ((size_t)b * IN_CH + (size_t)g * FPG) * plane;

    // ---- interior halo: 10 rows x 64 quads, 8-channel sum, no predication ----
#pragma unroll
    for (int it = 0; it < 5; it++) {
        const int q  = tid + it * NT;   // 0..639
        const int hy = q >> 6;
        const int qx = q & 63;
        int gy = ty0 + hy - 1;
        gy = (gy < 0) ? -gy : ((gy >= H_) ? 2 * H_ - 2 - gy : gy);
        const float4* p = (const float4*)(xg + (size_t)gy * W_) + qx;
        float4 a = p[0];
#pragma unroll
        for (int c = 1; c < FPG; c++) {
            float4 v = p[c * plane4];
            a.x += v.x; a.y += v.y; a.z += v.z; a.w += v.w;
        }
        *(float4*)&S[hy][4 + qx * 4] = a;
    }

    // ---- x-edge reflect columns: gx=-1 -> 1, gx=256 -> 254 (20 threads) ----
    if (tid >= 100 && tid < 100 + 2 * HYR) {
        const int e    = tid - 100;
        const int hy   = e >> 1;
        const int side = e & 1;
        int gy = ty0 + hy - 1;
        gy = (gy < 0) ? -gy : ((gy >= H_) ? 2 * H_ - 2 - gy : gy);
        const float* p = xg + (size_t)gy * W_ + (side ? (W_ - 2) : 1);
        float a = 0.f;
#pragma unroll
        for (int c = 0; c < FPG; c++) a += p[c * plane];
        S[hy][side ? (4 + W_) : 3] = a;
    }
    __syncthreads();

    // ---- compute: thread owns 4 cols x 4 rows x 8 oc ----
    const int px0 = (tid & 63) * 4;
    const int y0  = (tid >> 6) * 4;    // 0 or 4

    float* ob = out + ((size_t)b * OUT_CH + (size_t)g * OPG) * plane
                    + (size_t)(ty0 + y0) * W_ + px0;

    float w0[6], w1[6], w2[6];
#pragma unroll
    for (int k = 0; k < 6; k++) w0[k] = S[y0][3 + px0 + k];
#pragma unroll
    for (int k = 0; k < 6; k++) w1[k] = S[y0 + 1][3 + px0 + k];

#pragma unroll
    for (int rr = 0; rr < 4; rr++) {
#pragma unroll
        for (int k = 0; k < 6; k++) w2[k] = S[y0 + rr + 2][3 + px0 + k];

#pragma unroll
        for (int oc = 0; oc < OPG; oc++) {
            const float k0 = kw[oc][0], k1 = kw[oc][1], k2 = kw[oc][2];
            const float k3 = kw[oc][3], k4 = kw[oc][4], k5 = kw[oc][5];
            const float k6 = kw[oc][6], k7 = kw[oc][7], k8 = kw[oc][8];
            float4 v;
#pragma unroll
            for (int j = 0; j < 4; j++) {
                float a;
                a = w0[j] * k0;
                a = fmaf(w0[j + 1], k1, a);
                a = fmaf(w0[j + 2], k2, a);
                a = fmaf(w1[j],     k3, a);
                a = fmaf(w1[j + 1], k4, a);
                a = fmaf(w1[j + 2], k5, a);
                a = fmaf(w2[j],     k6, a);
                a = fmaf(w2[j + 1], k7, a);
                a = fmaf(w2[j + 2], k8, a);
                ((float*)&v)[j] = a;
            }
            *(float4*)(ob + (size_t)oc * plane + (size_t)rr * W_) = v;
        }

#pragma unroll
        for (int k = 0; k < 6; k++) { w0[k] = w1[k]; w1[k] = w2[k]; }
    }
}

extern "C" void kernel_launch(void* const* d_in, const int* in_sizes, int n_in,
                              void* d_out, int out_size) {
    const float* x   = (const float*)d_in[0];
    const float* rep = (const float*)d_in[1];
    const float* Wm  = (const float*)d_in[2];
    float* out = (float*)d_out;

    dim3 grid(H_ / TY, B_ * GROUPS);   // 32 x 64 = 2048 blocks, single wave
    dynconv_kernel<<<grid, NT>>>(x, rep, Wm, out);
}